// round 4
// baseline (speedup 1.0000x reference)
#include <cuda_runtime.h>

#define NN 100000
#define EE 3200000
#define DD 128
#define EPS 1e-5f

#define RB 64   // rows per GEMM block
#define TR 32   // rows per tile
#define SELF_BLOCKS ((NN + RB - 1) / RB)   // 1563
#define AGG_BLOCKS  SELF_BLOCKS            // interleaved 1:1
#define AGG_WARPS   (AGG_BLOCKS * 8)       // 12504

// Scratch (allocation-free rule: __device__ globals)
__device__ float g_neigh[NN * DD];   // mean-aggregated neighbor features
__device__ float g_rst[NN * DD];     // h@Ws + b, then post-relu activations
__device__ int   g_cnt[NN];          // degree histogram
__device__ int   g_off[NN];          // CSR exclusive offsets
__device__ int   g_cursor[NN];       // fill cursors
__device__ int   g_sorted[EE];       // src sorted by dst
__device__ float g_colsum[DD];
__device__ float g_colsumsq[DD];
__device__ float g_coefA[DD];
__device__ float g_coefB[DD];

// ---------------------------------------------------------------------------
// K0: zero counters + stats (no big zeroing any more)
// ---------------------------------------------------------------------------
__global__ void zero_kernel() {
    int i = blockIdx.x * blockDim.x + threadIdx.x;
    int stride = gridDim.x * blockDim.x;
    for (int f = i; f < NN; f += stride) g_cnt[f] = 0;
    if (i < DD) { g_colsum[i] = 0.f; g_colsumsq[i] = 0.f; }
}

// ---------------------------------------------------------------------------
// K1: degree histogram
// ---------------------------------------------------------------------------
__global__ void hist_kernel(const int* __restrict__ dst) {
    int i = blockIdx.x * blockDim.x + threadIdx.x;
    int stride = gridDim.x * blockDim.x;
    for (int e = i; e < EE; e += stride)
        atomicAdd(&g_cnt[__ldg(&dst[e])], 1);
}

// ---------------------------------------------------------------------------
// K2: single-block exclusive scan of g_cnt -> g_off (and g_cursor copy)
// ---------------------------------------------------------------------------
#define SCAN_T 1024
#define CHUNK  ((NN + SCAN_T - 1) / SCAN_T)   // 98
__global__ void __launch_bounds__(SCAN_T, 1)
scan_kernel() {
    __shared__ int ss[SCAN_T];
    int t = threadIdx.x;
    int beg = t * CHUNK;
    int end = min(beg + CHUNK, NN);
    int s = 0;
    for (int i = beg; i < end; i++) s += g_cnt[i];
    ss[t] = s;
    __syncthreads();
    for (int d = 1; d < SCAN_T; d <<= 1) {
        int v = (t >= d) ? ss[t - d] : 0;
        __syncthreads();
        ss[t] += v;
        __syncthreads();
    }
    int run = ss[t] - s;   // exclusive prefix of this chunk
    for (int i = beg; i < end; i++) {
        g_off[i] = run;
        g_cursor[i] = run;
        run += g_cnt[i];
    }
}

// ---------------------------------------------------------------------------
// K3: CSR fill — counting sort of src by dst
// ---------------------------------------------------------------------------
__global__ void fill_kernel(const int* __restrict__ src,
                            const int* __restrict__ dst) {
    int i = blockIdx.x * blockDim.x + threadIdx.x;
    int stride = gridDim.x * blockDim.x;
    for (int e = i; e < EE; e += stride) {
        int d = __ldg(&dst[e]);
        int p = atomicAdd(&g_cursor[d], 1);
        g_sorted[p] = __ldg(&src[e]);
    }
}

// ---------------------------------------------------------------------------
// K4 (fused, role-interleaved): odd blocks do CSR gather-aggregation into
// g_neigh (mem-bound); even blocks compute g_rst = h @ W_self + b (FMA-bound).
// Parity interleave keeps one of each on every SM -> real overlap.
// ---------------------------------------------------------------------------
__device__ __forceinline__ void f4add(float4& a, const float4 b) {
    a.x += b.x; a.y += b.y; a.z += b.z; a.w += b.w;
}

__global__ void __launch_bounds__(256, 2)
fused_agg_self(const float* __restrict__ h,
               const float* __restrict__ Wself,
               const float* __restrict__ bias) {
    extern __shared__ float sm[];

    if (blockIdx.x & 1) {
        // ----- aggregation role: warp per node, lane = float4 chunk -----
        int lane = threadIdx.x & 31;
        int gw = (blockIdx.x >> 1) * 8 + (threadIdx.x >> 5);
        const float4* h4 = (const float4*)h;
        for (int row = gw; row < NN; row += AGG_WARPS) {
            int beg = __ldg(&g_off[row]);
            int deg = __ldg(&g_cnt[row]);
            float4 a0 = make_float4(0.f, 0.f, 0.f, 0.f);
            float4 a1 = a0, a2 = a0, a3 = a0;
            int j = 0;
            for (; j + 4 <= deg; j += 4) {
                int s0 = __ldg(&g_sorted[beg + j]);
                int s1 = __ldg(&g_sorted[beg + j + 1]);
                int s2 = __ldg(&g_sorted[beg + j + 2]);
                int s3 = __ldg(&g_sorted[beg + j + 3]);
                f4add(a0, h4[(long long)s0 * 32 + lane]);
                f4add(a1, h4[(long long)s1 * 32 + lane]);
                f4add(a2, h4[(long long)s2 * 32 + lane]);
                f4add(a3, h4[(long long)s3 * 32 + lane]);
            }
            for (; j < deg; j++) {
                int s = __ldg(&g_sorted[beg + j]);
                f4add(a0, h4[(long long)s * 32 + lane]);
            }
            float inv = 1.0f / fmaxf((float)deg, 1.0f);
            float4 r;
            r.x = (a0.x + a1.x + a2.x + a3.x) * inv;
            r.y = (a0.y + a1.y + a2.y + a3.y) * inv;
            r.z = (a0.z + a1.z + a2.z + a3.z) * inv;
            r.w = (a0.w + a1.w + a2.w + a3.w) * inv;
            ((float4*)(g_neigh + (long long)row * DD))[lane] = r;
        }
        return;
    }

    // ----- self-GEMM role: g_rst = h @ Ws + b -----
    float* sWs = sm;            // 16384 floats (64 KB)
    float* sh  = sm + 16384;    // 4096 floats (16 KB)

    int t  = threadIdx.x;
    int cg = t & 31;
    int rg = t >> 5;
    int c0 = cg * 4;
    int gb = blockIdx.x >> 1;

    {
        const float4* w1 = (const float4*)Wself;
        float4* s1 = (float4*)sWs;
        for (int f = t; f < 4096; f += 256) s1[f] = w1[f];
    }

    float4 bv = ((const float4*)bias)[cg];

    for (int tt = 0; tt < RB / TR; tt++) {
        int row_base = gb * RB + tt * TR;
        __syncthreads();
        for (int f = t; f < TR * 32; f += 256) {
            int r  = f >> 5;
            int c4 = f & 31;
            int row = row_base + r;
            float4 hv = make_float4(0.f, 0.f, 0.f, 0.f);
            if (row < NN)
                hv = ((const float4*)(h + (long long)row * DD))[c4];
            ((float4*)sh)[f] = hv;
        }
        __syncthreads();

        float acc[4][4];
        #pragma unroll
        for (int r = 0; r < 4; r++)
            #pragma unroll
            for (int c = 0; c < 4; c++) acc[r][c] = 0.f;

        int r0 = rg * 4;
        for (int k = 0; k < 128; k += 4) {
            float wa[4][4];
            #pragma unroll
            for (int i = 0; i < 4; i++) {
                float4 x = *(const float4*)&sWs[(k + i) * 128 + c0];
                wa[i][0] = x.x; wa[i][1] = x.y; wa[i][2] = x.z; wa[i][3] = x.w;
            }
            #pragma unroll
            for (int r = 0; r < 4; r++) {
                float4 hx = *(const float4*)&sh[(r0 + r) * 128 + k];
                float hv[4] = {hx.x, hx.y, hx.z, hx.w};
                #pragma unroll
                for (int i = 0; i < 4; i++)
                    #pragma unroll
                    for (int c = 0; c < 4; c++)
                        acc[r][c] += hv[i] * wa[i][c];
            }
        }

        #pragma unroll
        for (int r = 0; r < 4; r++) {
            int row = row_base + r0 + r;
            if (row < NN) {
                ((float4*)(g_rst + (long long)row * DD))[cg] =
                    make_float4(acc[r][0] + bv.x, acc[r][1] + bv.y,
                                acc[r][2] + bv.z, acc[r][3] + bv.w);
            }
        }
    }
}

// ---------------------------------------------------------------------------
// K5: rst = relu(g_rst + g_neigh @ Wn); fused BN column stats.
// ---------------------------------------------------------------------------
__global__ void __launch_bounds__(256, 2)
neigh_gemm_kernel(const float* __restrict__ Wneigh) {
    extern __shared__ float sm[];
    float* sWn  = sm;                    // 16384 floats
    float* sn   = sm + 16384;            // 4096
    float* sred = sm + 16384 + 4096;     // 2048

    int t  = threadIdx.x;
    int cg = t & 31;
    int rg = t >> 5;
    int c0 = cg * 4;

    {
        const float4* w2 = (const float4*)Wneigh;
        float4* s2 = (float4*)sWn;
        for (int f = t; f < 4096; f += 256) s2[f] = w2[f];
    }

    float lsum[4] = {0.f, 0.f, 0.f, 0.f};
    float lsq[4]  = {0.f, 0.f, 0.f, 0.f};

    for (int tt = 0; tt < RB / TR; tt++) {
        int row_base = blockIdx.x * RB + tt * TR;
        __syncthreads();
        for (int f = t; f < TR * 32; f += 256) {
            int r  = f >> 5;
            int c4 = f & 31;
            int row = row_base + r;
            float4 nv = make_float4(0.f, 0.f, 0.f, 0.f);
            if (row < NN)
                nv = ((const float4*)(g_neigh + (long long)row * DD))[c4];
            ((float4*)sn)[f] = nv;
        }
        __syncthreads();

        float acc[4][4];
        #pragma unroll
        for (int r = 0; r < 4; r++)
            #pragma unroll
            for (int c = 0; c < 4; c++) acc[r][c] = 0.f;

        int r0 = rg * 4;
        for (int k = 0; k < 128; k += 4) {
            float wb[4][4];
            #pragma unroll
            for (int i = 0; i < 4; i++) {
                float4 y = *(const float4*)&sWn[(k + i) * 128 + c0];
                wb[i][0] = y.x; wb[i][1] = y.y; wb[i][2] = y.z; wb[i][3] = y.w;
            }
            #pragma unroll
            for (int r = 0; r < 4; r++) {
                float4 nx = *(const float4*)&sn[(r0 + r) * 128 + k];
                float nv[4] = {nx.x, nx.y, nx.z, nx.w};
                #pragma unroll
                for (int i = 0; i < 4; i++)
                    #pragma unroll
                    for (int c = 0; c < 4; c++)
                        acc[r][c] += nv[i] * wb[i][c];
            }
        }

        #pragma unroll
        for (int r = 0; r < 4; r++) {
            int row = row_base + r0 + r;
            if (row < NN) {
                float4* rp = ((float4*)(g_rst + (long long)row * DD)) + cg;
                float4 sv = *rp;
                float v0 = fmaxf(acc[r][0] + sv.x, 0.f);
                float v1 = fmaxf(acc[r][1] + sv.y, 0.f);
                float v2 = fmaxf(acc[r][2] + sv.z, 0.f);
                float v3 = fmaxf(acc[r][3] + sv.w, 0.f);
                lsum[0] += v0; lsq[0] += v0 * v0;
                lsum[1] += v1; lsq[1] += v1 * v1;
                lsum[2] += v2; lsq[2] += v2 * v2;
                lsum[3] += v3; lsq[3] += v3 * v3;
                *rp = make_float4(v0, v1, v2, v3);
            }
        }
    }

    __syncthreads();
    #pragma unroll
    for (int c = 0; c < 4; c++) {
        sred[rg * 128 + c0 + c]        = lsum[c];
        sred[1024 + rg * 128 + c0 + c] = lsq[c];
    }
    __syncthreads();
    {
        int stat = t >> 7;
        int c    = t & 127;
        float s = 0.f;
        #pragma unroll
        for (int g = 0; g < 8; g++) s += sred[stat * 1024 + g * 128 + c];
        if (stat == 0) atomicAdd(&g_colsum[c], s);
        else           atomicAdd(&g_colsumsq[c], s);
    }
}

// ---------------------------------------------------------------------------
// K6: finalize BN coefficients
// ---------------------------------------------------------------------------
__global__ void finalize_kernel(const float* __restrict__ gamma,
                                const float* __restrict__ beta) {
    int c = threadIdx.x;
    const float invN = 1.0f / (float)NN;
    float mean = g_colsum[c] * invN;
    float var  = g_colsumsq[c] * invN - mean * mean;
    float a = gamma[c] * rsqrtf(var + EPS);
    g_coefA[c] = a;
    g_coefB[c] = beta[c] - mean * a;
}

// ---------------------------------------------------------------------------
// K7: out = h + rst * A[c] + B[c]
// ---------------------------------------------------------------------------
__global__ void output_kernel(const float* __restrict__ h,
                              float* __restrict__ out) {
    int i = blockIdx.x * blockDim.x + threadIdx.x;
    int stride = gridDim.x * blockDim.x;
    const int nf4 = NN * DD / 4;
    for (int f = i; f < nf4; f += stride) {
        int cg = f & 31;
        float4 a  = ((const float4*)g_coefA)[cg];
        float4 bb = ((const float4*)g_coefB)[cg];
        float4 hv = ((const float4*)h)[f];
        float4 rv = ((const float4*)g_rst)[f];
        float4 o;
        o.x = hv.x + rv.x * a.x + bb.x;
        o.y = hv.y + rv.y * a.y + bb.y;
        o.z = hv.z + rv.z * a.z + bb.z;
        o.w = hv.w + rv.w * a.w + bb.w;
        ((float4*)out)[f] = o;
    }
}

// ---------------------------------------------------------------------------
extern "C" void kernel_launch(void* const* d_in, const int* in_sizes, int n_in,
                              void* d_out, int out_size) {
    const float* h      = (const float*)d_in[0];
    const int*   src    = (const int*)d_in[1];
    const int*   dst    = (const int*)d_in[2];
    const float* Wself  = (const float*)d_in[3];
    const float* Wneigh = (const float*)d_in[4];
    const float* bias   = (const float*)d_in[5];
    const float* gamma  = (const float*)d_in[6];
    const float* beta   = (const float*)d_in[7];
    float*       out    = (float*)d_out;

    zero_kernel<<<256, 256>>>();
    hist_kernel<<<4096, 256>>>(dst);
    scan_kernel<<<1, SCAN_T>>>();
    fill_kernel<<<4096, 256>>>(src, dst);

    const int fused_smem = 20480 * 4;   // 81920 B: sWs + sh
    cudaFuncSetAttribute(fused_agg_self,
                         cudaFuncAttributeMaxDynamicSharedMemorySize,
                         fused_smem);
    fused_agg_self<<<SELF_BLOCKS + AGG_BLOCKS, 256, fused_smem>>>(h, Wself, bias);

    const int neigh_smem = 22528 * 4;   // 90112 B
    cudaFuncSetAttribute(neigh_gemm_kernel,
                         cudaFuncAttributeMaxDynamicSharedMemorySize,
                         neigh_smem);
    neigh_gemm_kernel<<<(NN + RB - 1) / RB, 256, neigh_smem>>>(Wneigh);

    finalize_kernel<<<1, DD>>>(gamma, beta);
    output_kernel<<<2048, 256>>>(h, out);
}

// round 6
// speedup vs baseline: 1.0587x; 1.0587x over previous
#include <cuda_runtime.h>

#define NN 100000
#define EE 3200000
#define DD 128
#define EPS 1e-5f

#define RB 64                               // rows per GEMM block
#define GEMM_BLOCKS ((NN + RB - 1) / RB)    // 1563

// Scratch (allocation-free rule: __device__ globals)
__device__ float g_neigh[NN * DD];   // mean-aggregated neighbor features
__device__ float g_rst[NN * DD];     // post-relu activations
__device__ int   g_cnt[NN];          // degree histogram
__device__ int   g_off[NN];          // CSR exclusive offsets
__device__ int   g_cursor[NN];       // fill cursors
__device__ int   g_sorted[EE];       // src sorted by dst
__device__ float g_colsum[DD];
__device__ float g_colsumsq[DD];
__device__ float g_coefA[DD];
__device__ float g_coefB[DD];

// ---------------------------------------------------------------------------
// K0: zero counters + stats
// ---------------------------------------------------------------------------
__global__ void zero_kernel() {
    int i = blockIdx.x * blockDim.x + threadIdx.x;
    int stride = gridDim.x * blockDim.x;
    for (int f = i; f < NN; f += stride) g_cnt[f] = 0;
    if (i < DD) { g_colsum[i] = 0.f; g_colsumsq[i] = 0.f; }
}

// ---------------------------------------------------------------------------
// K1: degree histogram (int4 edge loads for MLP)
// ---------------------------------------------------------------------------
__global__ void hist_kernel(const int* __restrict__ dst) {
    int i = blockIdx.x * blockDim.x + threadIdx.x;
    int stride = gridDim.x * blockDim.x;
    const int4* d4 = (const int4*)dst;
    const int n4 = EE / 4;
    for (int e = i; e < n4; e += stride) {
        int4 d = __ldg(&d4[e]);
        atomicAdd(&g_cnt[d.x], 1);
        atomicAdd(&g_cnt[d.y], 1);
        atomicAdd(&g_cnt[d.z], 1);
        atomicAdd(&g_cnt[d.w], 1);
    }
}

// ---------------------------------------------------------------------------
// K2: single-block exclusive scan of g_cnt -> g_off / g_cursor
// ---------------------------------------------------------------------------
#define SCAN_T 1024
#define CHUNK  ((NN + SCAN_T - 1) / SCAN_T)   // 98
__global__ void __launch_bounds__(SCAN_T, 1)
scan_kernel() {
    __shared__ int ss[SCAN_T];
    int t = threadIdx.x;
    int beg = t * CHUNK;
    int end = min(beg + CHUNK, NN);
    int s = 0;
    for (int i = beg; i < end; i++) s += g_cnt[i];
    ss[t] = s;
    __syncthreads();
    for (int d = 1; d < SCAN_T; d <<= 1) {
        int v = (t >= d) ? ss[t - d] : 0;
        __syncthreads();
        ss[t] += v;
        __syncthreads();
    }
    int run = ss[t] - s;
    for (int i = beg; i < end; i++) {
        g_off[i] = run;
        g_cursor[i] = run;
        run += g_cnt[i];
    }
}

// ---------------------------------------------------------------------------
// K3: CSR fill — counting sort of src by dst (int4 loads)
// ---------------------------------------------------------------------------
__global__ void fill_kernel(const int* __restrict__ src,
                            const int* __restrict__ dst) {
    int i = blockIdx.x * blockDim.x + threadIdx.x;
    int stride = gridDim.x * blockDim.x;
    const int4* s4 = (const int4*)src;
    const int4* d4 = (const int4*)dst;
    const int n4 = EE / 4;
    for (int e = i; e < n4; e += stride) {
        int4 d = __ldg(&d4[e]);
        int4 s = __ldg(&s4[e]);
        g_sorted[atomicAdd(&g_cursor[d.x], 1)] = s.x;
        g_sorted[atomicAdd(&g_cursor[d.y], 1)] = s.y;
        g_sorted[atomicAdd(&g_cursor[d.z], 1)] = s.z;
        g_sorted[atomicAdd(&g_cursor[d.w], 1)] = s.w;
    }
}

// ---------------------------------------------------------------------------
// K4: aggregation — warp per node, lane = float4 chunk, unroll 8.
// No smem -> high occupancy -> enough MLP to hit the LTS bandwidth cap.
// ---------------------------------------------------------------------------
__device__ __forceinline__ void f4add(float4& a, const float4 b) {
    a.x += b.x; a.y += b.y; a.z += b.z; a.w += b.w;
}

__global__ void __launch_bounds__(256)
agg_kernel(const float* __restrict__ h) {
    int lane = threadIdx.x & 31;
    int gw = blockIdx.x * 8 + (threadIdx.x >> 5);
    int nw = gridDim.x * 8;
    const float4* h4 = (const float4*)h;
    for (int row = gw; row < NN; row += nw) {
        int beg = __ldg(&g_off[row]);
        int deg = __ldg(&g_cnt[row]);
        float4 a0 = make_float4(0.f, 0.f, 0.f, 0.f);
        float4 a1 = a0, a2 = a0, a3 = a0;
        int j = 0;
        for (; j + 8 <= deg; j += 8) {
            int s0 = __ldg(&g_sorted[beg + j]);
            int s1 = __ldg(&g_sorted[beg + j + 1]);
            int s2 = __ldg(&g_sorted[beg + j + 2]);
            int s3 = __ldg(&g_sorted[beg + j + 3]);
            int s4 = __ldg(&g_sorted[beg + j + 4]);
            int s5 = __ldg(&g_sorted[beg + j + 5]);
            int s6 = __ldg(&g_sorted[beg + j + 6]);
            int s7 = __ldg(&g_sorted[beg + j + 7]);
            float4 v0 = h4[(long long)s0 * 32 + lane];
            float4 v1 = h4[(long long)s1 * 32 + lane];
            float4 v2 = h4[(long long)s2 * 32 + lane];
            float4 v3 = h4[(long long)s3 * 32 + lane];
            float4 v4 = h4[(long long)s4 * 32 + lane];
            float4 v5 = h4[(long long)s5 * 32 + lane];
            float4 v6 = h4[(long long)s6 * 32 + lane];
            float4 v7 = h4[(long long)s7 * 32 + lane];
            f4add(a0, v0); f4add(a1, v1); f4add(a2, v2); f4add(a3, v3);
            f4add(a0, v4); f4add(a1, v5); f4add(a2, v6); f4add(a3, v7);
        }
        for (; j < deg; j++) {
            int s = __ldg(&g_sorted[beg + j]);
            f4add(a0, h4[(long long)s * 32 + lane]);
        }
        float inv = 1.0f / fmaxf((float)deg, 1.0f);
        float4 r;
        r.x = (a0.x + a1.x + a2.x + a3.x) * inv;
        r.y = (a0.y + a1.y + a2.y + a3.y) * inv;
        r.z = (a0.z + a1.z + a2.z + a3.z) * inv;
        r.w = (a0.w + a1.w + a2.w + a3.w) * inv;
        ((float4*)(g_neigh + (long long)row * DD))[lane] = r;
    }
}

// ---------------------------------------------------------------------------
// K5: dual GEMM: rst = relu(h@Ws + neigh@Wn + b), fused BN column stats.
// 512 threads = 16 row-warps x 32 col-threads; 64 rows per block, one tile.
// smem: Ws 64K + Wn 64K + h-tile 32K + n-tile 32K = 196608 B (1 CTA/SM).
// ---------------------------------------------------------------------------
__global__ void __launch_bounds__(512, 1)
dual_gemm_kernel(const float* __restrict__ h,
                 const float* __restrict__ Wself,
                 const float* __restrict__ Wneigh,
                 const float* __restrict__ bias) {
    extern __shared__ float sm[];
    float* sWs = sm;                 // 16384 floats
    float* sWn = sm + 16384;         // 16384
    float* sh  = sm + 32768;         // 8192 (64 x 128)
    float* sn  = sm + 40960;         // 8192
    // stats reduction reuses sh after the mainloop

    int t  = threadIdx.x;
    int cg = t & 31;        // cols 4*cg..4*cg+3
    int rg = t >> 5;        // warp id 0..15 -> rows 4*rg..4*rg+3
    int c0 = cg * 4;
    int row_base = blockIdx.x * RB;

    // cooperative loads
    {
        const float4* w1 = (const float4*)Wself;
        const float4* w2 = (const float4*)Wneigh;
        float4* s1 = (float4*)sWs;
        float4* s2 = (float4*)sWn;
        #pragma unroll
        for (int f = t; f < 4096; f += 512) { s1[f] = w1[f]; s2[f] = w2[f]; }
        for (int f = t; f < 2048; f += 512) {   // 64 rows x 32 float4
            int r  = f >> 5;
            int c4 = f & 31;
            int row = row_base + r;
            float4 hv = make_float4(0.f, 0.f, 0.f, 0.f);
            float4 nv = hv;
            if (row < NN) {
                hv = ((const float4*)(h + (long long)row * DD))[c4];
                nv = ((const float4*)(g_neigh + (long long)row * DD))[c4];
            }
            ((float4*)sh)[f] = hv;
            ((float4*)sn)[f] = nv;
        }
    }
    __syncthreads();

    float acc[4][4];
    #pragma unroll
    for (int r = 0; r < 4; r++)
        #pragma unroll
        for (int c = 0; c < 4; c++) acc[r][c] = 0.f;

    int r0 = rg * 4;
    for (int k = 0; k < 128; k += 4) {
        float wa[4][4], wb[4][4];
        #pragma unroll
        for (int i = 0; i < 4; i++) {
            float4 x = *(const float4*)&sWs[(k + i) * 128 + c0];
            wa[i][0] = x.x; wa[i][1] = x.y; wa[i][2] = x.z; wa[i][3] = x.w;
            float4 y = *(const float4*)&sWn[(k + i) * 128 + c0];
            wb[i][0] = y.x; wb[i][1] = y.y; wb[i][2] = y.z; wb[i][3] = y.w;
        }
        #pragma unroll
        for (int r = 0; r < 4; r++) {
            float4 hx = *(const float4*)&sh[(r0 + r) * 128 + k];
            float4 nx = *(const float4*)&sn[(r0 + r) * 128 + k];
            float hv[4] = {hx.x, hx.y, hx.z, hx.w};
            float nv[4] = {nx.x, nx.y, nx.z, nx.w};
            #pragma unroll
            for (int i = 0; i < 4; i++)
                #pragma unroll
                for (int c = 0; c < 4; c++)
                    acc[r][c] += hv[i] * wa[i][c] + nv[i] * wb[i][c];
        }
    }

    // epilogue: bias, relu, local stats, store
    float4 bv = ((const float4*)bias)[cg];
    float lsum[4] = {0.f, 0.f, 0.f, 0.f};
    float lsq[4]  = {0.f, 0.f, 0.f, 0.f};
    #pragma unroll
    for (int r = 0; r < 4; r++) {
        int row = row_base + r0 + r;
        if (row < NN) {
            float v0 = fmaxf(acc[r][0] + bv.x, 0.f);
            float v1 = fmaxf(acc[r][1] + bv.y, 0.f);
            float v2 = fmaxf(acc[r][2] + bv.z, 0.f);
            float v3 = fmaxf(acc[r][3] + bv.w, 0.f);
            lsum[0] += v0; lsq[0] += v0 * v0;
            lsum[1] += v1; lsq[1] += v1 * v1;
            lsum[2] += v2; lsq[2] += v2 * v2;
            lsum[3] += v3; lsq[3] += v3 * v3;
            ((float4*)(g_rst + (long long)row * DD))[cg] =
                make_float4(v0, v1, v2, v3);
        }
    }

    // block-reduce stats (reuse sh: 16 warps x 128 cols x 2 stats = 4096 f)
    __syncthreads();
    #pragma unroll
    for (int c = 0; c < 4; c++) {
        sh[rg * 128 + c0 + c]        = lsum[c];
        sh[2048 + rg * 128 + c0 + c] = lsq[c];
    }
    __syncthreads();
    if (t < 256) {
        int stat = t >> 7;       // 0: sum, 1: sumsq
        int c    = t & 127;
        float s = 0.f;
        #pragma unroll
        for (int g = 0; g < 16; g++) s += sh[stat * 2048 + g * 128 + c];
        if (stat == 0) atomicAdd(&g_colsum[c], s);
        else           atomicAdd(&g_colsumsq[c], s);
    }
}

// ---------------------------------------------------------------------------
// K6: finalize BN coefficients
// ---------------------------------------------------------------------------
__global__ void finalize_kernel(const float* __restrict__ gamma,
                                const float* __restrict__ beta) {
    int c = threadIdx.x;
    const float invN = 1.0f / (float)NN;
    float mean = g_colsum[c] * invN;
    float var  = g_colsumsq[c] * invN - mean * mean;
    float a = gamma[c] * rsqrtf(var + EPS);
    g_coefA[c] = a;
    g_coefB[c] = beta[c] - mean * a;
}

// ---------------------------------------------------------------------------
// K7: out = h + rst * A[c] + B[c]
// ---------------------------------------------------------------------------
__global__ void output_kernel(const float* __restrict__ h,
                              float* __restrict__ out) {
    int i = blockIdx.x * blockDim.x + threadIdx.x;
    int stride = gridDim.x * blockDim.x;
    const int nf4 = NN * DD / 4;
    for (int f = i; f < nf4; f += stride) {
        int cg = f & 31;
        float4 a  = ((const float4*)g_coefA)[cg];
        float4 bb = ((const float4*)g_coefB)[cg];
        float4 hv = ((const float4*)h)[f];
        float4 rv = ((const float4*)g_rst)[f];
        float4 o;
        o.x = hv.x + rv.x * a.x + bb.x;
        o.y = hv.y + rv.y * a.y + bb.y;
        o.z = hv.z + rv.z * a.z + bb.z;
        o.w = hv.w + rv.w * a.w + bb.w;
        ((float4*)out)[f] = o;
    }
}

// ---------------------------------------------------------------------------
extern "C" void kernel_launch(void* const* d_in, const int* in_sizes, int n_in,
                              void* d_out, int out_size) {
    const float* h      = (const float*)d_in[0];
    const int*   src    = (const int*)d_in[1];
    const int*   dst    = (const int*)d_in[2];
    const float* Wself  = (const float*)d_in[3];
    const float* Wneigh = (const float*)d_in[4];
    const float* bias   = (const float*)d_in[5];
    const float* gamma  = (const float*)d_in[6];
    const float* beta   = (const float*)d_in[7];
    float*       out    = (float*)d_out;

    zero_kernel<<<256, 256>>>();
    hist_kernel<<<2048, 256>>>(dst);
    scan_kernel<<<1, SCAN_T>>>();
    fill_kernel<<<2048, 256>>>(src, dst);
    agg_kernel<<<2048, 256>>>(h);

    const int gemm_smem = 49152 * 4;   // 196608 B
    cudaFuncSetAttribute(dual_gemm_kernel,
                         cudaFuncAttributeMaxDynamicSharedMemorySize,
                         gemm_smem);
    dual_gemm_kernel<<<GEMM_BLOCKS, 512, gemm_smem>>>(h, Wself, Wneigh, bias);

    finalize_kernel<<<1, DD>>>(gamma, beta);
    output_kernel<<<2048, 256>>>(h, out);
}

// round 7
// speedup vs baseline: 1.2767x; 1.2059x over previous
#include <cuda_runtime.h>
#include <cstdint>

#define NN 100000
#define EE 3200000
#define DD 128
#define EPS 1e-5f

#define RBM 64                               // rows per GEMM block
#define GEMM_BLOCKS ((NN + RBM - 1) / RBM)   // 1563

// smem layout for tf32 GEMM
#define SA_STRIDE 260                        // 256 + 4 pad
#define SB_STRIDE 136                        // 128 + 8 pad
#define SA_FLOATS (64 * SA_STRIDE)           // 16640
#define SB_FLOATS (256 * SB_STRIDE)          // 34816
#define GEMM_SMEM ((SA_FLOATS + SB_FLOATS) * 4)   // 205824 B

// Scratch (allocation-free rule: __device__ globals)
__device__ float g_neigh[NN * DD];   // mean-aggregated neighbor features
__device__ float g_rst[NN * DD];     // post-relu activations
__device__ int   g_cnt[NN];          // degree histogram
__device__ int   g_off[NN];          // CSR exclusive offsets
__device__ int   g_cursor[NN];       // fill cursors
__device__ int   g_sorted[EE];       // src sorted by dst
__device__ float g_colsum[DD];
__device__ float g_colsumsq[DD];
__device__ float g_coefA[DD];
__device__ float g_coefB[DD];

// ---------------------------------------------------------------------------
// K0: zero counters + stats
// ---------------------------------------------------------------------------
__global__ void zero_kernel() {
    int i = blockIdx.x * blockDim.x + threadIdx.x;
    int stride = gridDim.x * blockDim.x;
    for (int f = i; f < NN; f += stride) g_cnt[f] = 0;
    if (i < DD) { g_colsum[i] = 0.f; g_colsumsq[i] = 0.f; }
}

// ---------------------------------------------------------------------------
// K1: degree histogram (int4 edge loads for MLP)
// ---------------------------------------------------------------------------
__global__ void hist_kernel(const int* __restrict__ dst) {
    int i = blockIdx.x * blockDim.x + threadIdx.x;
    int stride = gridDim.x * blockDim.x;
    const int4* d4 = (const int4*)dst;
    const int n4 = EE / 4;
    for (int e = i; e < n4; e += stride) {
        int4 d = __ldg(&d4[e]);
        atomicAdd(&g_cnt[d.x], 1);
        atomicAdd(&g_cnt[d.y], 1);
        atomicAdd(&g_cnt[d.z], 1);
        atomicAdd(&g_cnt[d.w], 1);
    }
}

// ---------------------------------------------------------------------------
// K2: single-block exclusive scan of g_cnt -> g_off / g_cursor
// ---------------------------------------------------------------------------
#define SCAN_T 1024
#define CHUNK  ((NN + SCAN_T - 1) / SCAN_T)   // 98
__global__ void __launch_bounds__(SCAN_T, 1)
scan_kernel() {
    __shared__ int ss[SCAN_T];
    int t = threadIdx.x;
    int beg = t * CHUNK;
    int end = min(beg + CHUNK, NN);
    int s = 0;
    for (int i = beg; i < end; i++) s += g_cnt[i];
    ss[t] = s;
    __syncthreads();
    for (int d = 1; d < SCAN_T; d <<= 1) {
        int v = (t >= d) ? ss[t - d] : 0;
        __syncthreads();
        ss[t] += v;
        __syncthreads();
    }
    int run = ss[t] - s;
    for (int i = beg; i < end; i++) {
        g_off[i] = run;
        g_cursor[i] = run;
        run += g_cnt[i];
    }
}

// ---------------------------------------------------------------------------
// K3: CSR fill — counting sort of src by dst (int4 loads)
// ---------------------------------------------------------------------------
__global__ void fill_kernel(const int* __restrict__ src,
                            const int* __restrict__ dst) {
    int i = blockIdx.x * blockDim.x + threadIdx.x;
    int stride = gridDim.x * blockDim.x;
    const int4* s4 = (const int4*)src;
    const int4* d4 = (const int4*)dst;
    const int n4 = EE / 4;
    for (int e = i; e < n4; e += stride) {
        int4 d = __ldg(&d4[e]);
        int4 s = __ldg(&s4[e]);
        g_sorted[atomicAdd(&g_cursor[d.x], 1)] = s.x;
        g_sorted[atomicAdd(&g_cursor[d.y], 1)] = s.y;
        g_sorted[atomicAdd(&g_cursor[d.z], 1)] = s.z;
        g_sorted[atomicAdd(&g_cursor[d.w], 1)] = s.w;
    }
}

// ---------------------------------------------------------------------------
// K4: aggregation — warp per node, lane = float4 chunk, unroll 8.
// ---------------------------------------------------------------------------
__device__ __forceinline__ void f4add(float4& a, const float4 b) {
    a.x += b.x; a.y += b.y; a.z += b.z; a.w += b.w;
}

__global__ void __launch_bounds__(256)
agg_kernel(const float* __restrict__ h) {
    int lane = threadIdx.x & 31;
    int gw = blockIdx.x * 8 + (threadIdx.x >> 5);
    int nw = gridDim.x * 8;
    const float4* h4 = (const float4*)h;
    for (int row = gw; row < NN; row += nw) {
        int beg = __ldg(&g_off[row]);
        int deg = __ldg(&g_cnt[row]);
        float4 a0 = make_float4(0.f, 0.f, 0.f, 0.f);
        float4 a1 = a0, a2 = a0, a3 = a0;
        int j = 0;
        for (; j + 8 <= deg; j += 8) {
            int s0 = __ldg(&g_sorted[beg + j]);
            int s1 = __ldg(&g_sorted[beg + j + 1]);
            int s2 = __ldg(&g_sorted[beg + j + 2]);
            int s3 = __ldg(&g_sorted[beg + j + 3]);
            int s4 = __ldg(&g_sorted[beg + j + 4]);
            int s5 = __ldg(&g_sorted[beg + j + 5]);
            int s6 = __ldg(&g_sorted[beg + j + 6]);
            int s7 = __ldg(&g_sorted[beg + j + 7]);
            float4 v0 = h4[(long long)s0 * 32 + lane];
            float4 v1 = h4[(long long)s1 * 32 + lane];
            float4 v2 = h4[(long long)s2 * 32 + lane];
            float4 v3 = h4[(long long)s3 * 32 + lane];
            float4 v4 = h4[(long long)s4 * 32 + lane];
            float4 v5 = h4[(long long)s5 * 32 + lane];
            float4 v6 = h4[(long long)s6 * 32 + lane];
            float4 v7 = h4[(long long)s7 * 32 + lane];
            f4add(a0, v0); f4add(a1, v1); f4add(a2, v2); f4add(a3, v3);
            f4add(a0, v4); f4add(a1, v5); f4add(a2, v6); f4add(a3, v7);
        }
        for (; j < deg; j++) {
            int s = __ldg(&g_sorted[beg + j]);
            f4add(a0, h4[(long long)s * 32 + lane]);
        }
        float inv = 1.0f / fmaxf((float)deg, 1.0f);
        float4 r;
        r.x = (a0.x + a1.x + a2.x + a3.x) * inv;
        r.y = (a0.y + a1.y + a2.y + a3.y) * inv;
        r.z = (a0.z + a1.z + a2.z + a3.z) * inv;
        r.w = (a0.w + a1.w + a2.w + a3.w) * inv;
        ((float4*)(g_neigh + (long long)row * DD))[lane] = r;
    }
}

// ---------------------------------------------------------------------------
// K5: TF32 tensor-core dual GEMM (concat K=256):
//   rst = relu([h | neigh] @ [Ws; Wn] + b), fused BN column stats.
// Block: 256 threads (8 warps, 2x4 warp grid), tile 64 rows x 128 cols.
// mma.sync.m16n8k8.tf32; warp tile 32x32 = 2x4 fragments.
// ---------------------------------------------------------------------------
__device__ __forceinline__ uint32_t f2tf32(float v) {
    uint32_t x;
    asm("cvt.rna.tf32.f32 %0, %1;" : "=r"(x) : "f"(v));
    return x;
}

__global__ void __launch_bounds__(256, 1)
dual_gemm_tf32(const float* __restrict__ h,
               const float* __restrict__ Wself,
               const float* __restrict__ Wneigh,
               const float* __restrict__ bias) {
    extern __shared__ float sm[];
    float* sA = sm;              // 64 x SA_STRIDE
    float* sB = sm + SA_FLOATS;  // 256 x SB_STRIDE

    const int t    = threadIdx.x;
    const int lane = t & 31;
    const int wid  = t >> 5;
    const int gid  = lane >> 2;   // 0..7
    const int tig  = lane & 3;    // 0..3
    const int wm   = wid & 1;     // warp row 0..1
    const int wn   = wid >> 1;    // warp col 0..3
    const int row_base = blockIdx.x * RBM;

    // --- cooperative A load: 64 rows x 256 cols = [h | neigh], cvt tf32 ---
    for (int f = t; f < 64 * 64; f += 256) {       // 64 float4 per row
        int r  = f >> 6;
        int c4 = f & 63;
        int row = row_base + r;
        float4 v = make_float4(0.f, 0.f, 0.f, 0.f);
        if (row < NN) {
            if (c4 < 32) v = ((const float4*)(h + (size_t)row * DD))[c4];
            else         v = ((const float4*)(g_neigh + (size_t)row * DD))[c4 - 32];
        }
        float* p = &sA[r * SA_STRIDE + c4 * 4];
        p[0] = __uint_as_float(f2tf32(v.x));
        p[1] = __uint_as_float(f2tf32(v.y));
        p[2] = __uint_as_float(f2tf32(v.z));
        p[3] = __uint_as_float(f2tf32(v.w));
    }
    // --- cooperative B load: rows 0..127 = Ws, 128..255 = Wn ---
    for (int f = t; f < 256 * 32; f += 256) {      // 32 float4 per row
        int k  = f >> 5;
        int n4 = f & 31;
        const float4* W = (k < 128) ? (const float4*)Wself : (const float4*)Wneigh;
        float4 v = __ldg(&W[(k & 127) * 32 + n4]);
        float* p = &sB[k * SB_STRIDE + n4 * 4];
        p[0] = __uint_as_float(f2tf32(v.x));
        p[1] = __uint_as_float(f2tf32(v.y));
        p[2] = __uint_as_float(f2tf32(v.z));
        p[3] = __uint_as_float(f2tf32(v.w));
    }
    __syncthreads();

    float acc[2][4][4];
    #pragma unroll
    for (int mi = 0; mi < 2; mi++)
        #pragma unroll
        for (int ni = 0; ni < 4; ni++)
            #pragma unroll
            for (int c = 0; c < 4; c++) acc[mi][ni][c] = 0.f;

    for (int k = 0; k < 256; k += 8) {
        uint32_t a[2][4], b[4][2];
        #pragma unroll
        for (int mi = 0; mi < 2; mi++) {
            int r0 = wm * 32 + mi * 16 + gid;
            a[mi][0] = __float_as_uint(sA[r0 * SA_STRIDE + k + tig]);
            a[mi][1] = __float_as_uint(sA[(r0 + 8) * SA_STRIDE + k + tig]);
            a[mi][2] = __float_as_uint(sA[r0 * SA_STRIDE + k + tig + 4]);
            a[mi][3] = __float_as_uint(sA[(r0 + 8) * SA_STRIDE + k + tig + 4]);
        }
        #pragma unroll
        for (int ni = 0; ni < 4; ni++) {
            int n0 = wn * 32 + ni * 8 + gid;
            b[ni][0] = __float_as_uint(sB[(k + tig) * SB_STRIDE + n0]);
            b[ni][1] = __float_as_uint(sB[(k + tig + 4) * SB_STRIDE + n0]);
        }
        #pragma unroll
        for (int mi = 0; mi < 2; mi++)
            #pragma unroll
            for (int ni = 0; ni < 4; ni++) {
                asm volatile(
                    "mma.sync.aligned.m16n8k8.row.col.f32.tf32.tf32.f32 "
                    "{%0,%1,%2,%3}, {%4,%5,%6,%7}, {%8,%9}, {%0,%1,%2,%3};"
                    : "+f"(acc[mi][ni][0]), "+f"(acc[mi][ni][1]),
                      "+f"(acc[mi][ni][2]), "+f"(acc[mi][ni][3])
                    : "r"(a[mi][0]), "r"(a[mi][1]), "r"(a[mi][2]), "r"(a[mi][3]),
                      "r"(b[ni][0]), "r"(b[ni][1]));
            }
    }

    // --- epilogue: bias, relu, store, per-thread BN stats ---
    float2 bv[4];
    #pragma unroll
    for (int ni = 0; ni < 4; ni++) {
        int col = wn * 32 + ni * 8 + 2 * tig;
        bv[ni] = *(const float2*)&bias[col];
    }

    float lsum[4][2], lsq[4][2];
    #pragma unroll
    for (int ni = 0; ni < 4; ni++) {
        lsum[ni][0] = lsum[ni][1] = 0.f;
        lsq[ni][0] = lsq[ni][1] = 0.f;
    }

    #pragma unroll
    for (int mi = 0; mi < 2; mi++) {
        #pragma unroll
        for (int half = 0; half < 2; half++) {
            int row = row_base + wm * 32 + mi * 16 + half * 8 + gid;
            if (row < NN) {
                #pragma unroll
                for (int ni = 0; ni < 4; ni++) {
                    int col = wn * 32 + ni * 8 + 2 * tig;
                    float v0 = fmaxf(acc[mi][ni][half * 2]     + bv[ni].x, 0.f);
                    float v1 = fmaxf(acc[mi][ni][half * 2 + 1] + bv[ni].y, 0.f);
                    lsum[ni][0] += v0; lsq[ni][0] += v0 * v0;
                    lsum[ni][1] += v1; lsq[ni][1] += v1 * v1;
                    *(float2*)&g_rst[(size_t)row * DD + col] = make_float2(v0, v1);
                }
            }
        }
    }

    // warp-reduce stats over gid lanes (lane bits 2..4), then global atomics
    #pragma unroll
    for (int ni = 0; ni < 4; ni++)
        #pragma unroll
        for (int s = 0; s < 2; s++) {
            #pragma unroll
            for (int off = 4; off <= 16; off <<= 1) {
                lsum[ni][s] += __shfl_xor_sync(0xffffffffu, lsum[ni][s], off);
                lsq[ni][s]  += __shfl_xor_sync(0xffffffffu, lsq[ni][s],  off);
            }
        }
    if (gid == 0) {   // lanes 0..3 hold warp totals for their 8 columns
        #pragma unroll
        for (int ni = 0; ni < 4; ni++) {
            int col = wn * 32 + ni * 8 + 2 * tig;
            atomicAdd(&g_colsum[col],       lsum[ni][0]);
            atomicAdd(&g_colsum[col + 1],   lsum[ni][1]);
            atomicAdd(&g_colsumsq[col],     lsq[ni][0]);
            atomicAdd(&g_colsumsq[col + 1], lsq[ni][1]);
        }
    }
}

// ---------------------------------------------------------------------------
// K6: finalize BN coefficients
// ---------------------------------------------------------------------------
__global__ void finalize_kernel(const float* __restrict__ gamma,
                                const float* __restrict__ beta) {
    int c = threadIdx.x;
    const float invN = 1.0f / (float)NN;
    float mean = g_colsum[c] * invN;
    float var  = g_colsumsq[c] * invN - mean * mean;
    float a = gamma[c] * rsqrtf(var + EPS);
    g_coefA[c] = a;
    g_coefB[c] = beta[c] - mean * a;
}

// ---------------------------------------------------------------------------
// K7: out = h + rst * A[c] + B[c]
// ---------------------------------------------------------------------------
__global__ void output_kernel(const float* __restrict__ h,
                              float* __restrict__ out) {
    int i = blockIdx.x * blockDim.x + threadIdx.x;
    int stride = gridDim.x * blockDim.x;
    const int nf4 = NN * DD / 4;
    for (int f = i; f < nf4; f += stride) {
        int cg = f & 31;
        float4 a  = ((const float4*)g_coefA)[cg];
        float4 bb = ((const float4*)g_coefB)[cg];
        float4 hv = ((const float4*)h)[f];
        float4 rv = ((const float4*)g_rst)[f];
        float4 o;
        o.x = hv.x + rv.x * a.x + bb.x;
        o.y = hv.y + rv.y * a.y + bb.y;
        o.z = hv.z + rv.z * a.z + bb.z;
        o.w = hv.w + rv.w * a.w + bb.w;
        ((float4*)out)[f] = o;
    }
}

// ---------------------------------------------------------------------------
extern "C" void kernel_launch(void* const* d_in, const int* in_sizes, int n_in,
                              void* d_out, int out_size) {
    const float* h      = (const float*)d_in[0];
    const int*   src    = (const int*)d_in[1];
    const int*   dst    = (const int*)d_in[2];
    const float* Wself  = (const float*)d_in[3];
    const float* Wneigh = (const float*)d_in[4];
    const float* bias   = (const float*)d_in[5];
    const float* gamma  = (const float*)d_in[6];
    const float* beta   = (const float*)d_in[7];
    float*       out    = (float*)d_out;

    zero_kernel<<<256, 256>>>();
    hist_kernel<<<2048, 256>>>(dst);
    scan_kernel<<<1, SCAN_T>>>();
    fill_kernel<<<2048, 256>>>(src, dst);
    agg_kernel<<<2048, 256>>>(h);

    cudaFuncSetAttribute(dual_gemm_tf32,
                         cudaFuncAttributeMaxDynamicSharedMemorySize,
                         GEMM_SMEM);
    dual_gemm_tf32<<<GEMM_BLOCKS, 256, GEMM_SMEM>>>(h, Wself, Wneigh, bias);

    finalize_kernel<<<1, DD>>>(gamma, beta);
    output_kernel<<<2048, 256>>>(h, out);
}